// round 8
// baseline (speedup 1.0000x reference)
#include <cuda_runtime.h>
#include <cuda_fp16.h>

#define MAXV 100000
#define MAXE 300000
#define MAXB 16
#define MAXN (MAXB * MAXV)

// ---- scratch (static __device__ per harness rules) ----
__device__ int    g_cnt[MAXV];
__device__ int    g_cur[MAXV];
__device__ int    g_rowptr[MAXV + 1];
__device__ int    g_part[128];
__device__ int2   g_cw[MAXE];          // (col, w-as-int) fused: one 8B load per neighbor
__device__ float  g_dinv[MAXV];
__device__ __align__(16) __half g_xT[(size_t)MAXV * MAXB * 4];   // xT[v][b][0..3] half (8B/node)
__device__ float4 g_v4[MAXN];                                    // (b,v) displaced verts fp32
__device__ __align__(16) __half g_h1[(size_t)MAXV * MAXB * 16];  // h[v][b][c]
__device__ __align__(16) __half g_h2[(size_t)MAXV * MAXB * 16];

// ---------------- CSR build ----------------
__global__ void zero_kernel(int V) {
    int i = blockIdx.x * blockDim.x + threadIdx.x;
    if (i < V) { g_cnt[i] = 0; g_cur[i] = 0; }
}

__global__ void count_kernel(const int* __restrict__ edges, int E) {
    int e = blockIdx.x * blockDim.x + threadIdx.x;
    if (e < E) atomicAdd(&g_cnt[edges[2 * e + 1]], 1);
}

// scanA also produces dinv (reads g_cnt anyway)
__global__ void scanA_kernel(int V) {
    __shared__ int sh[1024];
    int t = threadIdx.x;
    int i = blockIdx.x * 1024 + t;
    int val = (i < V) ? g_cnt[i] : 0;
    if (i < V) g_dinv[i] = rsqrtf((float)val + 1.0f);  // +1 self-loop
    sh[t] = val;
    __syncthreads();
    for (int off = 1; off < 1024; off <<= 1) {
        int add = (t >= off) ? sh[t - off] : 0;
        __syncthreads();
        sh[t] += add;
        __syncthreads();
    }
    if (i < V) g_rowptr[i] = sh[t] - val;
    if (t == 1023) g_part[blockIdx.x] = sh[1023];
}

__global__ void scanB_kernel(int nblocks, int V) {
    __shared__ int sh[128];
    int t = threadIdx.x;
    int val = (t < nblocks) ? g_part[t] : 0;
    sh[t] = val;
    __syncthreads();
    for (int off = 1; off < 128; off <<= 1) {
        int add = (t >= off) ? sh[t - off] : 0;
        __syncthreads();
        sh[t] += add;
        __syncthreads();
    }
    g_part[t] = sh[t] - val;
    if (t == 127) g_rowptr[V] = sh[127];
}

__global__ void scanC_kernel(int V) {
    int i = blockIdx.x * blockDim.x + threadIdx.x;
    if (i < V) g_rowptr[i] += g_part[i >> 10];
}

__global__ void scatter_kernel(const int* __restrict__ edges, int E) {
    int e = blockIdx.x * blockDim.x + threadIdx.x;
    if (e < E) {
        int s = edges[2 * e];
        int d = edges[2 * e + 1];
        int pos = g_rowptr[d] + atomicAdd(&g_cur[d], 1);
        float w = g_dinv[s] * g_dinv[d];
        g_cw[pos] = make_int2(s, __float_as_int(w));
    }
}

// Transpose x(b,v,3) -> xT[v][b] packed half (8B per (v,b)).
__global__ void padT_kernel(const float* __restrict__ x, int V, int N) {
    int n = blockIdx.x * blockDim.x + threadIdx.x;
    if (n >= N) return;
    int v = n % V, b = n / V;
    const float* p = x + (size_t)n * 3;
    __half2* dst = (__half2*)(g_xT + ((size_t)v * MAXB + b) * 4);
    dst[0] = __floats2half2_rn(p[0], p[1]);
    dst[1] = __floats2half2_rn(p[2], 0.f);
}

// ---------------- GCN layers: warp per vertex, all 16 batches ----------------
// lane t = 2*b + h ; thread handles batch b, channels [8h, 8h+8)

// Layer 1: xT -> h1[v][b][c]. Unconditional predicated chunk-4 gathers.
__global__ void layer1_kernel(const float* __restrict__ W1,
                              const float* __restrict__ b1, int V) {
    __shared__ float sW[48], sb[16];
    if (threadIdx.x < 48) sW[threadIdx.x] = W1[threadIdx.x];
    if (threadIdx.x < 16) sb[threadIdx.x] = b1[threadIdx.x];
    __syncthreads();
    int v = blockIdx.x * 8 + (threadIdx.x >> 5);
    if (v >= V) return;
    int t = threadIdx.x & 31;
    int b = t >> 1, h = t & 1;
    float di = __ldg(&g_dinv[v]);
    float swt = di * di;

    uint2 raw = *(const uint2*)(g_xT + ((size_t)v * MAXB + b) * 4);
    float2 f0 = __half22float2(*(__half2*)&raw.x);
    float2 f1 = __half22float2(*(__half2*)&raw.y);
    float a0 = swt * f0.x, a1 = swt * f0.y, a2 = swt * f1.x;

    int j0 = __ldg(&g_rowptr[v]);
    int r1 = __ldg(&g_rowptr[v + 1]);
    for (int j = j0; j < r1; j += 4) {
        int last = r1 - 1;
        int2 cw0 = __ldg(&g_cw[j]);
        int2 cw1 = __ldg(&g_cw[min(j + 1, last)]);
        int2 cw2 = __ldg(&g_cw[min(j + 2, last)]);
        int2 cw3 = __ldg(&g_cw[min(j + 3, last)]);
        float w0 = __int_as_float(cw0.y);
        float w1 = (j + 1 <= last) ? __int_as_float(cw1.y) : 0.f;
        float w2 = (j + 2 <= last) ? __int_as_float(cw2.y) : 0.f;
        float w3 = (j + 3 <= last) ? __int_as_float(cw3.y) : 0.f;
        uint2 ra = *(const uint2*)(g_xT + ((size_t)cw0.x * MAXB + b) * 4);
        uint2 rb = *(const uint2*)(g_xT + ((size_t)cw1.x * MAXB + b) * 4);
        uint2 rc = *(const uint2*)(g_xT + ((size_t)cw2.x * MAXB + b) * 4);
        uint2 rd = *(const uint2*)(g_xT + ((size_t)cw3.x * MAXB + b) * 4);
        float2 g0, g1;
        g0 = __half22float2(*(__half2*)&ra.x); g1 = __half22float2(*(__half2*)&ra.y);
        a0 += w0 * g0.x; a1 += w0 * g0.y; a2 += w0 * g1.x;
        g0 = __half22float2(*(__half2*)&rb.x); g1 = __half22float2(*(__half2*)&rb.y);
        a0 += w1 * g0.x; a1 += w1 * g0.y; a2 += w1 * g1.x;
        g0 = __half22float2(*(__half2*)&rc.x); g1 = __half22float2(*(__half2*)&rc.y);
        a0 += w2 * g0.x; a1 += w2 * g0.y; a2 += w2 * g1.x;
        g0 = __half22float2(*(__half2*)&rd.x); g1 = __half22float2(*(__half2*)&rd.y);
        a0 += w3 * g0.x; a1 += w3 * g0.y; a2 += w3 * g1.x;
    }
    __half2 o[4];
#pragma unroll
    for (int i = 0; i < 4; i++) {
        int c0 = h * 8 + 2 * i, c1 = c0 + 1;
        float t0 = sb[c0] + a0 * sW[c0] + a1 * sW[16 + c0] + a2 * sW[32 + c0];
        float t1 = sb[c1] + a0 * sW[c1] + a1 * sW[16 + c1] + a2 * sW[32 + c1];
        t0 = t0 > 0.f ? t0 : 0.01f * t0;
        t1 = t1 > 0.f ? t1 : 0.01f * t1;
        o[i] = __floats2half2_rn(t0, t1);
    }
    *(uint4*)(g_h1 + (size_t)v * 256 + t * 8) = *(uint4*)o;  // 512B coalesced per warp
}

// Accumulate one 32B row (uint4 of half2) into agg[8] with weight w.
__device__ __forceinline__ void acc_row(float* agg, uint4 raw, float w) {
    __half2* hp = (__half2*)&raw;
#pragma unroll
    for (int i = 0; i < 4; i++) {
        float2 f = __half22float2(hp[i]);
        agg[2 * i] += w * f.x;
        agg[2 * i + 1] += w * f.y;
    }
}

// Gather with unconditional predicated chunk-4 MLP over [v][256] half array.
__device__ __forceinline__ void gather_agg(const __half* __restrict__ src,
                                           float* agg, int v, int t, float swt) {
    {
        uint4 raw = *(const uint4*)(src + (size_t)v * 256 + t * 8);
        __half2* hp = (__half2*)&raw;
#pragma unroll
        for (int i = 0; i < 4; i++) {
            float2 f = __half22float2(hp[i]);
            agg[2 * i] = swt * f.x;
            agg[2 * i + 1] = swt * f.y;
        }
    }
    int j0 = __ldg(&g_rowptr[v]);
    int r1 = __ldg(&g_rowptr[v + 1]);
    for (int j = j0; j < r1; j += 4) {
        int last = r1 - 1;
        int2 cw0 = __ldg(&g_cw[j]);
        int2 cw1 = __ldg(&g_cw[min(j + 1, last)]);
        int2 cw2 = __ldg(&g_cw[min(j + 2, last)]);
        int2 cw3 = __ldg(&g_cw[min(j + 3, last)]);
        float w0 = __int_as_float(cw0.y);
        float w1 = (j + 1 <= last) ? __int_as_float(cw1.y) : 0.f;
        float w2 = (j + 2 <= last) ? __int_as_float(cw2.y) : 0.f;
        float w3 = (j + 3 <= last) ? __int_as_float(cw3.y) : 0.f;
        uint4 ra = *(const uint4*)(src + (size_t)cw0.x * 256 + t * 8);
        uint4 rb = *(const uint4*)(src + (size_t)cw1.x * 256 + t * 8);
        uint4 rc = *(const uint4*)(src + (size_t)cw2.x * 256 + t * 8);
        uint4 rd = *(const uint4*)(src + (size_t)cw3.x * 256 + t * 8);
        acc_row(agg, ra, w0);
        acc_row(agg, rb, w1);
        acc_row(agg, rc, w2);
        acc_row(agg, rd, w3);
    }
}

// Layer 2: h1 -> h2.
__global__ void layer2_kernel(const float* __restrict__ W2,
                              const float* __restrict__ b2, int V) {
    __shared__ float sW[256], sb[16];
    sW[threadIdx.x] = W2[threadIdx.x];
    if (threadIdx.x < 16) sb[threadIdx.x] = b2[threadIdx.x];
    __syncthreads();
    int v = blockIdx.x * 8 + (threadIdx.x >> 5);
    if (v >= V) return;
    int t = threadIdx.x & 31;
    int h = t & 1;
    float di = __ldg(&g_dinv[v]);
    float agg[8];
    gather_agg(g_h1, agg, v, t, di * di);

    float po[16];
#pragma unroll
    for (int c = 0; c < 16; c++) {
        float acc = 0.f;
#pragma unroll
        for (int i = 0; i < 8; i++) acc += agg[i] * sW[(h * 8 + i) * 16 + c];
        po[c] = acc;
    }
    __half2 o[4];
#pragma unroll
    for (int i = 0; i < 4; i++) {
        int c0 = h * 8 + 2 * i, c1 = c0 + 1;
        int pc0 = (1 - h) * 8 + 2 * i, pc1 = pc0 + 1;
        float r0 = __shfl_xor_sync(0xFFFFFFFFu, po[pc0], 1);
        float r1v = __shfl_xor_sync(0xFFFFFFFFu, po[pc1], 1);
        float t0 = po[c0] + r0 + sb[c0];
        float t1 = po[c1] + r1v + sb[c1];
        t0 = t0 > 0.f ? t0 : 0.01f * t0;
        t1 = t1 > 0.f ? t1 : 0.01f * t1;
        o[i] = __floats2half2_rn(t0, t1);
    }
    *(uint4*)(g_h2 + (size_t)v * 256 + t * 8) = *(uint4*)o;
}

// Layer 3: h2 -> offs(3); v = x + offs; writes d_out and g_v4 (b,v layout).
__global__ void layer3_kernel(const float* __restrict__ x,
                              const float* __restrict__ W3,
                              const float* __restrict__ b3,
                              float* __restrict__ out, int V, int E) {
    __shared__ float sW[48], sb[3];
    if (threadIdx.x < 48) sW[threadIdx.x] = W3[threadIdx.x];
    if (threadIdx.x < 3) sb[threadIdx.x] = b3[threadIdx.x];
    __syncthreads();
    int v = blockIdx.x * 8 + (threadIdx.x >> 5);
    if (v >= V) return;
    int t = threadIdx.x & 31;
    int b = t >> 1, h = t & 1;
    float di = __ldg(&g_dinv[v]);
    float agg[8];
    gather_agg(g_h2, agg, v, t, di * di);

    float po[3];
#pragma unroll
    for (int p = 0; p < 3; p++) {
        float acc = 0.f;
#pragma unroll
        for (int i = 0; i < 8; i++) acc += agg[i] * sW[(h * 8 + i) * 3 + p];
        po[p] = acc;
    }
    float offs[3];
#pragma unroll
    for (int p = 0; p < 3; p++)
        offs[p] = po[p] + __shfl_xor_sync(0xFFFFFFFFu, po[p], 1) + sb[p];

    if (h == 0) {
        size_t n = (size_t)b * V + v;
        const float* xr = x + n * 3;  // fp32 original verts (output-critical)
        float vx = offs[0] + xr[0];
        float vy = offs[1] + xr[1];
        float vz = offs[2] + xr[2];
        size_t o = ((size_t)b * (V + E) + v) * 3;
        out[o + 0] = vx;
        out[o + 1] = vy;
        out[o + 2] = vz;
        g_v4[n] = make_float4(vx, vy, vz, 0.f);
    }
}

// Midpoints: mid[b][e] = (v[b][src] + v[b][dst]) / 2. 2D grid, float4 gathers.
__global__ void mid_kernel(const int* __restrict__ edges, float* __restrict__ out,
                           int V, int E) {
    int e = blockIdx.x * blockDim.x + threadIdx.x;
    if (e >= E) return;
    int b = blockIdx.y;
    int2 sd = *(const int2*)(edges + 2 * e);
    int base = b * V;
    float4 vs = g_v4[base + sd.x];
    float4 vd = g_v4[base + sd.y];
    float* m = out + ((size_t)b * (V + E) + V + (size_t)e) * 3;
    m[0] = 0.5f * (vs.x + vd.x);
    m[1] = 0.5f * (vs.y + vd.y);
    m[2] = 0.5f * (vs.z + vd.z);
}

// Broadcast faces across B (float4-vectorized; exact below 2^24).
__global__ void faces_kernel(const int* __restrict__ faces, float* __restrict__ out,
                             int perB, int B) {
    int i4 = blockIdx.x * blockDim.x + threadIdx.x;
    int n4 = perB >> 2;
    if (i4 < n4) {
        int4 f = ((const int4*)faces)[i4];
        float4 vf = make_float4((float)f.x, (float)f.y, (float)f.z, (float)f.w);
#pragma unroll
        for (int b = 0; b < MAXB; b++)
            if (b < B) ((float4*)(out + (size_t)b * perB))[i4] = vf;
    } else {
        int i = (n4 << 2) + (i4 - n4);  // scalar tail
        if (i < perB) {
            float vf = (float)faces[i];
            for (int b = 0; b < B; b++) out[(size_t)b * perB + i] = vf;
        }
    }
}

extern "C" void kernel_launch(void* const* d_in, const int* in_sizes, int n_in,
                              void* d_out, int out_size) {
    const float* verts = (const float*)d_in[0];
    const int*   edges = (const int*)d_in[1];
    const int*   faces = (const int*)d_in[2];
    const float* W1 = (const float*)d_in[3];
    const float* b1 = (const float*)d_in[4];
    const float* W2 = (const float*)d_in[5];
    const float* b2 = (const float*)d_in[6];
    const float* W3 = (const float*)d_in[7];
    const float* b3 = (const float*)d_in[8];
    float* out = (float*)d_out;

    const int B = 16;
    int E = in_sizes[1] / 2;
    int Fsub = in_sizes[2] / 3;
    int V = in_sizes[0] / (B * 3);
    int N = B * V;
    int nScanBlocks = (V + 1023) / 1024;

    // CSR build (per-batch graph identical; build once over V,E)
    zero_kernel<<<(V + 255) / 256, 256>>>(V);
    count_kernel<<<(E + 255) / 256, 256>>>(edges, E);
    scanA_kernel<<<nScanBlocks, 1024>>>(V);
    scanB_kernel<<<1, 128>>>(nScanBlocks, V);
    scanC_kernel<<<(V + 255) / 256, 256>>>(V);
    scatter_kernel<<<(E + 255) / 256, 256>>>(edges, E);
    padT_kernel<<<(N + 255) / 256, 256>>>(verts, V, N);

    // GCN layers: warp per vertex, all batches at once
    int vblocks = (V + 7) / 8;
    layer1_kernel<<<vblocks, 256>>>(W1, b1, V);
    layer2_kernel<<<vblocks, 256>>>(W2, b2, V);
    layer3_kernel<<<vblocks, 256>>>(verts, W3, b3, out, V, E);

    // Midpoints
    dim3 midGrid((E + 255) / 256, B);
    mid_kernel<<<midGrid, 256>>>(edges, out, V, E);

    // Faces broadcast
    long long vertsOut = (long long)B * (V + E) * 3;
    long long facesOut = (long long)B * Fsub * 3;
    if ((long long)out_size >= vertsOut + facesOut) {
        int perB = Fsub * 3;
        int n4 = perB / 4;
        int totalThreads = n4 + (perB - n4 * 4);
        faces_kernel<<<(totalThreads + 255) / 256, 256>>>(faces, out + vertsOut, perB, B);
    }
}

// round 11
// speedup vs baseline: 1.0445x; 1.0445x over previous
#include <cuda_runtime.h>
#include <cuda_fp16.h>

#define MAXV 100000
#define MAXE 300000
#define MAXB 16
#define MAXN (MAXB * MAXV)

// ---- scratch (static __device__ per harness rules) ----
__device__ int    g_cnt[MAXV];
__device__ int    g_cur[MAXV];
__device__ int    g_rowptr[MAXV + 1];
__device__ int    g_part[128];
__device__ int2   g_cw[MAXE];          // (col, w-as-int) fused: one 8B load per neighbor
__device__ float  g_dinv[MAXV];
__device__ __align__(16) __half g_xT[(size_t)MAXV * MAXB * 4];   // xT[v][b][0..3] half (8B/node)
__device__ float4 g_v4[MAXN];                                    // (b,v) displaced verts fp32
__device__ __align__(16) __half g_h1[(size_t)MAXV * MAXB * 16];  // h[v][b][c]
__device__ __align__(16) __half g_h2[(size_t)MAXV * MAXB * 16];

// ---------------- CSR build ----------------
__global__ void zero_kernel(int V) {
    int i = blockIdx.x * blockDim.x + threadIdx.x;
    if (i < V) { g_cnt[i] = 0; g_cur[i] = 0; }
}

__global__ void count_kernel(const int* __restrict__ edges, int E) {
    int e = blockIdx.x * blockDim.x + threadIdx.x;
    if (e < E) atomicAdd(&g_cnt[edges[2 * e + 1]], 1);
}

// scanA also produces dinv (reads g_cnt anyway)
__global__ void scanA_kernel(int V) {
    __shared__ int sh[1024];
    int t = threadIdx.x;
    int i = blockIdx.x * 1024 + t;
    int val = (i < V) ? g_cnt[i] : 0;
    if (i < V) g_dinv[i] = rsqrtf((float)val + 1.0f);  // +1 self-loop
    sh[t] = val;
    __syncthreads();
    for (int off = 1; off < 1024; off <<= 1) {
        int add = (t >= off) ? sh[t - off] : 0;
        __syncthreads();
        sh[t] += add;
        __syncthreads();
    }
    if (i < V) g_rowptr[i] = sh[t] - val;
    if (t == 1023) g_part[blockIdx.x] = sh[1023];
}

__global__ void scanB_kernel(int nblocks, int V) {
    __shared__ int sh[128];
    int t = threadIdx.x;
    int val = (t < nblocks) ? g_part[t] : 0;
    sh[t] = val;
    __syncthreads();
    for (int off = 1; off < 128; off <<= 1) {
        int add = (t >= off) ? sh[t - off] : 0;
        __syncthreads();
        sh[t] += add;
        __syncthreads();
    }
    g_part[t] = sh[t] - val;
    if (t == 127) g_rowptr[V] = sh[127];
}

__global__ void scanC_kernel(int V) {
    int i = blockIdx.x * blockDim.x + threadIdx.x;
    if (i < V) g_rowptr[i] += g_part[i >> 10];
}

__global__ void scatter_kernel(const int* __restrict__ edges, int E) {
    int e = blockIdx.x * blockDim.x + threadIdx.x;
    if (e < E) {
        int s = edges[2 * e];
        int d = edges[2 * e + 1];
        int pos = g_rowptr[d] + atomicAdd(&g_cur[d], 1);
        float w = g_dinv[s] * g_dinv[d];
        g_cw[pos] = make_int2(s, __float_as_int(w));
    }
}

// Transpose x(b,v,3) -> xT[v][b] packed half (8B per (v,b)).
__global__ void padT_kernel(const float* __restrict__ x, int V, int N) {
    int n = blockIdx.x * blockDim.x + threadIdx.x;
    if (n >= N) return;
    int v = n % V, b = n / V;
    const float* p = x + (size_t)n * 3;
    __half2* dst = (__half2*)(g_xT + ((size_t)v * MAXB + b) * 4);
    dst[0] = __floats2half2_rn(p[0], p[1]);
    dst[1] = __floats2half2_rn(p[2], 0.f);
}

// ---------------- GCN layers: warp per vertex, all 16 batches ----------------
// lane t = 2*b + h ; thread handles batch b, channels [8h, 8h+8)

// Layer 1: xT -> h1[v][b][c]. Chunk-4 + tail gathers (R7 structure).
__global__ void layer1_kernel(const float* __restrict__ W1,
                              const float* __restrict__ b1, int V) {
    __shared__ float sW[48], sb[16];
    if (threadIdx.x < 48) sW[threadIdx.x] = W1[threadIdx.x];
    if (threadIdx.x < 16) sb[threadIdx.x] = b1[threadIdx.x];
    __syncthreads();
    int v = blockIdx.x * 8 + (threadIdx.x >> 5);
    if (v >= V) return;
    int t = threadIdx.x & 31;
    int b = t >> 1, h = t & 1;
    float di = __ldg(&g_dinv[v]);
    float swt = di * di;

    uint2 raw = *(const uint2*)(g_xT + ((size_t)v * MAXB + b) * 4);
    float2 f0 = __half22float2(*(__half2*)&raw.x);
    float2 f1 = __half22float2(*(__half2*)&raw.y);
    float a0 = swt * f0.x, a1 = swt * f0.y, a2 = swt * f1.x;

    int j = __ldg(&g_rowptr[v]);
    int r1 = __ldg(&g_rowptr[v + 1]);
    for (; j + 4 <= r1; j += 4) {
        int2 cw0 = __ldg(&g_cw[j]);
        int2 cw1 = __ldg(&g_cw[j + 1]);
        int2 cw2 = __ldg(&g_cw[j + 2]);
        int2 cw3 = __ldg(&g_cw[j + 3]);
        uint2 ra = *(const uint2*)(g_xT + ((size_t)cw0.x * MAXB + b) * 4);
        uint2 rb = *(const uint2*)(g_xT + ((size_t)cw1.x * MAXB + b) * 4);
        uint2 rc = *(const uint2*)(g_xT + ((size_t)cw2.x * MAXB + b) * 4);
        uint2 rd = *(const uint2*)(g_xT + ((size_t)cw3.x * MAXB + b) * 4);
        float w0 = __int_as_float(cw0.y), w1 = __int_as_float(cw1.y);
        float w2 = __int_as_float(cw2.y), w3 = __int_as_float(cw3.y);
        float2 g0, g1;
        g0 = __half22float2(*(__half2*)&ra.x); g1 = __half22float2(*(__half2*)&ra.y);
        a0 += w0 * g0.x; a1 += w0 * g0.y; a2 += w0 * g1.x;
        g0 = __half22float2(*(__half2*)&rb.x); g1 = __half22float2(*(__half2*)&rb.y);
        a0 += w1 * g0.x; a1 += w1 * g0.y; a2 += w1 * g1.x;
        g0 = __half22float2(*(__half2*)&rc.x); g1 = __half22float2(*(__half2*)&rc.y);
        a0 += w2 * g0.x; a1 += w2 * g0.y; a2 += w2 * g1.x;
        g0 = __half22float2(*(__half2*)&rd.x); g1 = __half22float2(*(__half2*)&rd.y);
        a0 += w3 * g0.x; a1 += w3 * g0.y; a2 += w3 * g1.x;
    }
    for (; j < r1; j++) {
        int2 cw = __ldg(&g_cw[j]);
        float w = __int_as_float(cw.y);
        uint2 nb = *(const uint2*)(g_xT + ((size_t)cw.x * MAXB + b) * 4);
        float2 g0 = __half22float2(*(__half2*)&nb.x);
        float2 g1 = __half22float2(*(__half2*)&nb.y);
        a0 += w * g0.x; a1 += w * g0.y; a2 += w * g1.x;
    }
    __half2 o[4];
#pragma unroll
    for (int i = 0; i < 4; i++) {
        int c0 = h * 8 + 2 * i, c1 = c0 + 1;
        float t0 = sb[c0] + a0 * sW[c0] + a1 * sW[16 + c0] + a2 * sW[32 + c0];
        float t1 = sb[c1] + a0 * sW[c1] + a1 * sW[16 + c1] + a2 * sW[32 + c1];
        t0 = t0 > 0.f ? t0 : 0.01f * t0;
        t1 = t1 > 0.f ? t1 : 0.01f * t1;
        o[i] = __floats2half2_rn(t0, t1);
    }
    *(uint4*)(g_h1 + (size_t)v * 256 + t * 8) = *(uint4*)o;  // 512B coalesced per warp
}

// Accumulate one 32B row (uint4 of half2) into agg[8] with weight w.
__device__ __forceinline__ void acc_row(float* agg, uint4 raw, float w) {
    __half2* hp = (__half2*)&raw;
#pragma unroll
    for (int i = 0; i < 4; i++) {
        float2 f = __half22float2(hp[i]);
        agg[2 * i] += w * f.x;
        agg[2 * i + 1] += w * f.y;
    }
}

// Gather loop with chunk-4 MLP + scalar tail over [v][256] half array.
__device__ __forceinline__ void gather_agg(const __half* __restrict__ src,
                                           float* agg, int v, int t, float swt) {
    {
        uint4 raw = *(const uint4*)(src + (size_t)v * 256 + t * 8);
        __half2* hp = (__half2*)&raw;
#pragma unroll
        for (int i = 0; i < 4; i++) {
            float2 f = __half22float2(hp[i]);
            agg[2 * i] = swt * f.x;
            agg[2 * i + 1] = swt * f.y;
        }
    }
    int j = __ldg(&g_rowptr[v]);
    int r1 = __ldg(&g_rowptr[v + 1]);
    for (; j + 4 <= r1; j += 4) {
        int2 cw0 = __ldg(&g_cw[j]);
        int2 cw1 = __ldg(&g_cw[j + 1]);
        int2 cw2 = __ldg(&g_cw[j + 2]);
        int2 cw3 = __ldg(&g_cw[j + 3]);
        uint4 ra = *(const uint4*)(src + (size_t)cw0.x * 256 + t * 8);
        uint4 rb = *(const uint4*)(src + (size_t)cw1.x * 256 + t * 8);
        uint4 rc = *(const uint4*)(src + (size_t)cw2.x * 256 + t * 8);
        uint4 rd = *(const uint4*)(src + (size_t)cw3.x * 256 + t * 8);
        acc_row(agg, ra, __int_as_float(cw0.y));
        acc_row(agg, rb, __int_as_float(cw1.y));
        acc_row(agg, rc, __int_as_float(cw2.y));
        acc_row(agg, rd, __int_as_float(cw3.y));
    }
    for (; j < r1; j++) {
        int2 cw = __ldg(&g_cw[j]);
        uint4 raw = *(const uint4*)(src + (size_t)cw.x * 256 + t * 8);
        acc_row(agg, raw, __int_as_float(cw.y));
    }
}

// Layer 2: h1 -> h2.
__global__ void layer2_kernel(const float* __restrict__ W2,
                              const float* __restrict__ b2, int V) {
    __shared__ float sW[256], sb[16];
    sW[threadIdx.x] = W2[threadIdx.x];
    if (threadIdx.x < 16) sb[threadIdx.x] = b2[threadIdx.x];
    __syncthreads();
    int v = blockIdx.x * 8 + (threadIdx.x >> 5);
    if (v >= V) return;
    int t = threadIdx.x & 31;
    int h = t & 1;
    float di = __ldg(&g_dinv[v]);
    float agg[8];
    gather_agg(g_h1, agg, v, t, di * di);

    float po[16];
#pragma unroll
    for (int c = 0; c < 16; c++) {
        float acc = 0.f;
#pragma unroll
        for (int i = 0; i < 8; i++) acc += agg[i] * sW[(h * 8 + i) * 16 + c];
        po[c] = acc;
    }
    __half2 o[4];
#pragma unroll
    for (int i = 0; i < 4; i++) {
        int c0 = h * 8 + 2 * i, c1 = c0 + 1;
        int pc0 = (1 - h) * 8 + 2 * i, pc1 = pc0 + 1;
        float r0 = __shfl_xor_sync(0xFFFFFFFFu, po[pc0], 1);
        float r1v = __shfl_xor_sync(0xFFFFFFFFu, po[pc1], 1);
        float t0 = po[c0] + r0 + sb[c0];
        float t1 = po[c1] + r1v + sb[c1];
        t0 = t0 > 0.f ? t0 : 0.01f * t0;
        t1 = t1 > 0.f ? t1 : 0.01f * t1;
        o[i] = __floats2half2_rn(t0, t1);
    }
    *(uint4*)(g_h2 + (size_t)v * 256 + t * 8) = *(uint4*)o;
}

// Layer 3: h2 -> offs(3); v = x + offs; writes d_out and g_v4 (b,v layout).
__global__ void layer3_kernel(const float* __restrict__ x,
                              const float* __restrict__ W3,
                              const float* __restrict__ b3,
                              float* __restrict__ out, int V, int E) {
    __shared__ float sW[48], sb[3];
    if (threadIdx.x < 48) sW[threadIdx.x] = W3[threadIdx.x];
    if (threadIdx.x < 3) sb[threadIdx.x] = b3[threadIdx.x];
    __syncthreads();
    int v = blockIdx.x * 8 + (threadIdx.x >> 5);
    if (v >= V) return;
    int t = threadIdx.x & 31;
    int b = t >> 1, h = t & 1;
    float di = __ldg(&g_dinv[v]);
    float agg[8];
    gather_agg(g_h2, agg, v, t, di * di);

    float po[3];
#pragma unroll
    for (int p = 0; p < 3; p++) {
        float acc = 0.f;
#pragma unroll
        for (int i = 0; i < 8; i++) acc += agg[i] * sW[(h * 8 + i) * 3 + p];
        po[p] = acc;
    }
    float offs[3];
#pragma unroll
    for (int p = 0; p < 3; p++)
        offs[p] = po[p] + __shfl_xor_sync(0xFFFFFFFFu, po[p], 1) + sb[p];

    if (h == 0) {
        size_t n = (size_t)b * V + v;
        const float* xr = x + n * 3;  // fp32 original verts (output-critical)
        float vx = offs[0] + xr[0];
        float vy = offs[1] + xr[1];
        float vz = offs[2] + xr[2];
        size_t o = ((size_t)b * (V + E) + v) * 3;
        out[o + 0] = vx;
        out[o + 1] = vy;
        out[o + 2] = vz;
        g_v4[n] = make_float4(vx, vy, vz, 0.f);
    }
}

// Midpoints: one thread per edge, loop over all batches.
// Edges read ONCE (not 16x); 32 independent L2 gathers per thread (high MLP).
__global__ void mid_kernel(const int* __restrict__ edges, float* __restrict__ out,
                           int V, int E) {
    int e = blockIdx.x * blockDim.x + threadIdx.x;
    if (e >= E) return;
    int2 sd = *(const int2*)(edges + 2 * e);
#pragma unroll 4
    for (int b = 0; b < MAXB; b++) {
        float4 vs = g_v4[b * MAXV + 0 * V + sd.x];  // placeholder replaced below
        (void)vs;
        break;
    }
#pragma unroll 4
    for (int b = 0; b < MAXB; b++) {
        float4 vs = g_v4[(size_t)b * V + sd.x];
        float4 vd = g_v4[(size_t)b * V + sd.y];
        float* m = out + ((size_t)b * (V + E) + V + (size_t)e) * 3;
        m[0] = 0.5f * (vs.x + vd.x);
        m[1] = 0.5f * (vs.y + vd.y);
        m[2] = 0.5f * (vs.z + vd.z);
    }
}

// Broadcast faces across B (float4-vectorized; exact below 2^24).
__global__ void faces_kernel(const int* __restrict__ faces, float* __restrict__ out,
                             int perB, int B) {
    int i4 = blockIdx.x * blockDim.x + threadIdx.x;
    int n4 = perB >> 2;
    if (i4 < n4) {
        int4 f = ((const int4*)faces)[i4];
        float4 vf = make_float4((float)f.x, (float)f.y, (float)f.z, (float)f.w);
#pragma unroll
        for (int b = 0; b < MAXB; b++)
            if (b < B) ((float4*)(out + (size_t)b * perB))[i4] = vf;
    } else {
        int i = (n4 << 2) + (i4 - n4);  // scalar tail
        if (i < perB) {
            float vf = (float)faces[i];
            for (int b = 0; b < B; b++) out[(size_t)b * perB + i] = vf;
        }
    }
}

extern "C" void kernel_launch(void* const* d_in, const int* in_sizes, int n_in,
                              void* d_out, int out_size) {
    const float* verts = (const float*)d_in[0];
    const int*   edges = (const int*)d_in[1];
    const int*   faces = (const int*)d_in[2];
    const float* W1 = (const float*)d_in[3];
    const float* b1 = (const float*)d_in[4];
    const float* W2 = (const float*)d_in[5];
    const float* b2 = (const float*)d_in[6];
    const float* W3 = (const float*)d_in[7];
    const float* b3 = (const float*)d_in[8];
    float* out = (float*)d_out;

    const int B = 16;
    int E = in_sizes[1] / 2;
    int Fsub = in_sizes[2] / 3;
    int V = in_sizes[0] / (B * 3);
    int N = B * V;
    int nScanBlocks = (V + 1023) / 1024;

    // Side stream + events for the independent faces branch (created once;
    // host-side objects only, no device memory).
    static cudaStream_t s2 = nullptr;
    static cudaEvent_t evFork = nullptr, evJoin = nullptr;
    if (s2 == nullptr) {
        cudaStreamCreateWithFlags(&s2, cudaStreamNonBlocking);
        cudaEventCreateWithFlags(&evFork, cudaEventDisableTiming);
        cudaEventCreateWithFlags(&evJoin, cudaEventDisableTiming);
    }

    long long vertsOut = (long long)B * (V + E) * 3;
    long long facesOut = (long long)B * Fsub * 3;
    bool doFaces = ((long long)out_size >= vertsOut + facesOut);

    // Fork: faces broadcast runs concurrently with the whole GCN chain.
    if (doFaces) {
        cudaEventRecord(evFork, 0);
        cudaStreamWaitEvent(s2, evFork, 0);
        int perB = Fsub * 3;
        int n4 = perB / 4;
        int totalThreads = n4 + (perB - n4 * 4);
        faces_kernel<<<(totalThreads + 255) / 256, 256, 0, s2>>>(
            faces, out + vertsOut, perB, B);
        cudaEventRecord(evJoin, s2);
    }

    // CSR build (per-batch graph identical; build once over V,E)
    zero_kernel<<<(V + 255) / 256, 256>>>(V);
    count_kernel<<<(E + 255) / 256, 256>>>(edges, E);
    scanA_kernel<<<nScanBlocks, 1024>>>(V);
    scanB_kernel<<<1, 128>>>(nScanBlocks, V);
    scanC_kernel<<<(V + 255) / 256, 256>>>(V);
    scatter_kernel<<<(E + 255) / 256, 256>>>(edges, E);
    padT_kernel<<<(N + 255) / 256, 256>>>(verts, V, N);

    // GCN layers: warp per vertex, all batches at once
    int vblocks = (V + 7) / 8;
    layer1_kernel<<<vblocks, 256>>>(W1, b1, V);
    layer2_kernel<<<vblocks, 256>>>(W2, b2, V);
    layer3_kernel<<<vblocks, 256>>>(verts, W3, b3, out, V, E);

    // Midpoints (edges read once; per-thread loop over batches)
    mid_kernel<<<(E + 255) / 256, 256>>>(edges, out, V, E);

    // Join the faces branch back into the main stream.
    if (doFaces) {
        cudaStreamWaitEvent(0, evJoin, 0);
    }
}

// round 13
// speedup vs baseline: 1.1092x; 1.0620x over previous
#include <cuda_runtime.h>
#include <cuda_fp16.h>

#define MAXV 100000
#define MAXE 300000
#define MAXB 16
#define MAXN (MAXB * MAXV)

// ---- scratch (static __device__ per harness rules) ----
__device__ int    g_cnt[MAXV];
__device__ int    g_cur[MAXV];
__device__ int    g_rowptr[MAXV + 1];
__device__ int    g_part[128];
__device__ int2   g_cw[MAXE];          // (col, w-as-int) fused: one 8B load per neighbor
__device__ float  g_dinv[MAXV];
__device__ __align__(16) __half g_xT[(size_t)MAXV * MAXB * 4];   // xT[v][b][0..3] half (8B/node)
__device__ float4 g_v4T[(size_t)MAXV * MAXB];                    // v4T[v][b] displaced verts fp32
__device__ __align__(16) __half g_h1[(size_t)MAXV * MAXB * 16];  // h[v][b][c]
__device__ __align__(16) __half g_h2[(size_t)MAXV * MAXB * 16];

// ---------------- CSR build ----------------
__global__ void zero_kernel(int V) {
    int i = blockIdx.x * blockDim.x + threadIdx.x;
    if (i < V) { g_cnt[i] = 0; g_cur[i] = 0; }
}

__global__ void count_kernel(const int* __restrict__ edges, int E) {
    int e = blockIdx.x * blockDim.x + threadIdx.x;
    if (e < E) atomicAdd(&g_cnt[edges[2 * e + 1]], 1);
}

// scanA also produces dinv (reads g_cnt anyway)
__global__ void scanA_kernel(int V) {
    __shared__ int sh[1024];
    int t = threadIdx.x;
    int i = blockIdx.x * 1024 + t;
    int val = (i < V) ? g_cnt[i] : 0;
    if (i < V) g_dinv[i] = rsqrtf((float)val + 1.0f);  // +1 self-loop
    sh[t] = val;
    __syncthreads();
    for (int off = 1; off < 1024; off <<= 1) {
        int add = (t >= off) ? sh[t - off] : 0;
        __syncthreads();
        sh[t] += add;
        __syncthreads();
    }
    if (i < V) g_rowptr[i] = sh[t] - val;
    if (t == 1023) g_part[blockIdx.x] = sh[1023];
}

__global__ void scanB_kernel(int nblocks, int V) {
    __shared__ int sh[128];
    int t = threadIdx.x;
    int val = (t < nblocks) ? g_part[t] : 0;
    sh[t] = val;
    __syncthreads();
    for (int off = 1; off < 128; off <<= 1) {
        int add = (t >= off) ? sh[t - off] : 0;
        __syncthreads();
        sh[t] += add;
        __syncthreads();
    }
    g_part[t] = sh[t] - val;
    if (t == 127) g_rowptr[V] = sh[127];
}

__global__ void scanC_kernel(int V) {
    int i = blockIdx.x * blockDim.x + threadIdx.x;
    if (i < V) g_rowptr[i] += g_part[i >> 10];
}

__global__ void scatter_kernel(const int* __restrict__ edges, int E) {
    int e = blockIdx.x * blockDim.x + threadIdx.x;
    if (e < E) {
        int s = edges[2 * e];
        int d = edges[2 * e + 1];
        int pos = g_rowptr[d] + atomicAdd(&g_cur[d], 1);
        float w = g_dinv[s] * g_dinv[d];
        g_cw[pos] = make_int2(s, __float_as_int(w));
    }
}

// Transpose x(b,v,3) -> xT[v][b] packed half via smem tile (coalesced writes).
// Block = 256 threads handles a 16-vertex x 16-batch tile.
__global__ void padT_kernel(const float* __restrict__ x, int V) {
    __shared__ uint2 tile[16][17];  // [vl][b], pad to dodge bank conflicts
    int v0 = blockIdx.x * 16;
    {
        int b = threadIdx.x >> 4;       // 0..15
        int vl = threadIdx.x & 15;      // 0..15
        int v = v0 + vl;
        uint2 val = make_uint2(0, 0);
        if (v < V) {
            const float* p = x + ((size_t)b * V + v) * 3;
            __half2 lo = __floats2half2_rn(p[0], p[1]);
            __half2 hi = __floats2half2_rn(p[2], 0.f);
            val = make_uint2(*(unsigned*)&lo, *(unsigned*)&hi);
        }
        tile[vl][b] = val;
    }
    __syncthreads();
    {
        int vl = threadIdx.x >> 4;
        int b = threadIdx.x & 15;
        int v = v0 + vl;
        if (v < V)
            *(uint2*)(g_xT + ((size_t)v * MAXB + b) * 4) = tile[vl][b];
    }
}

// ---------------- GCN layers: warp per vertex, all 16 batches ----------------
// lane t = 2*b + h ; thread handles batch b, channels [8h, 8h+8)

// Layer 1: xT -> h1[v][b][c]. Chunk-4 + tail gathers.
__global__ void layer1_kernel(const float* __restrict__ W1,
                              const float* __restrict__ b1, int V) {
    __shared__ float sW[48], sb[16];
    if (threadIdx.x < 48) sW[threadIdx.x] = W1[threadIdx.x];
    if (threadIdx.x < 16) sb[threadIdx.x] = b1[threadIdx.x];
    __syncthreads();
    int v = blockIdx.x * 8 + (threadIdx.x >> 5);
    if (v >= V) return;
    int t = threadIdx.x & 31;
    int b = t >> 1, h = t & 1;
    float di = __ldg(&g_dinv[v]);
    float swt = di * di;

    uint2 raw = *(const uint2*)(g_xT + ((size_t)v * MAXB + b) * 4);
    float2 f0 = __half22float2(*(__half2*)&raw.x);
    float2 f1 = __half22float2(*(__half2*)&raw.y);
    float a0 = swt * f0.x, a1 = swt * f0.y, a2 = swt * f1.x;

    int j = __ldg(&g_rowptr[v]);
    int r1 = __ldg(&g_rowptr[v + 1]);
    for (; j + 4 <= r1; j += 4) {
        int2 cw0 = __ldg(&g_cw[j]);
        int2 cw1 = __ldg(&g_cw[j + 1]);
        int2 cw2 = __ldg(&g_cw[j + 2]);
        int2 cw3 = __ldg(&g_cw[j + 3]);
        uint2 ra = *(const uint2*)(g_xT + ((size_t)cw0.x * MAXB + b) * 4);
        uint2 rb = *(const uint2*)(g_xT + ((size_t)cw1.x * MAXB + b) * 4);
        uint2 rc = *(const uint2*)(g_xT + ((size_t)cw2.x * MAXB + b) * 4);
        uint2 rd = *(const uint2*)(g_xT + ((size_t)cw3.x * MAXB + b) * 4);
        float w0 = __int_as_float(cw0.y), w1 = __int_as_float(cw1.y);
        float w2 = __int_as_float(cw2.y), w3 = __int_as_float(cw3.y);
        float2 g0, g1;
        g0 = __half22float2(*(__half2*)&ra.x); g1 = __half22float2(*(__half2*)&ra.y);
        a0 += w0 * g0.x; a1 += w0 * g0.y; a2 += w0 * g1.x;
        g0 = __half22float2(*(__half2*)&rb.x); g1 = __half22float2(*(__half2*)&rb.y);
        a0 += w1 * g0.x; a1 += w1 * g0.y; a2 += w1 * g1.x;
        g0 = __half22float2(*(__half2*)&rc.x); g1 = __half22float2(*(__half2*)&rc.y);
        a0 += w2 * g0.x; a1 += w2 * g0.y; a2 += w2 * g1.x;
        g0 = __half22float2(*(__half2*)&rd.x); g1 = __half22float2(*(__half2*)&rd.y);
        a0 += w3 * g0.x; a1 += w3 * g0.y; a2 += w3 * g1.x;
    }
    for (; j < r1; j++) {
        int2 cw = __ldg(&g_cw[j]);
        float w = __int_as_float(cw.y);
        uint2 nb = *(const uint2*)(g_xT + ((size_t)cw.x * MAXB + b) * 4);
        float2 g0 = __half22float2(*(__half2*)&nb.x);
        float2 g1 = __half22float2(*(__half2*)&nb.y);
        a0 += w * g0.x; a1 += w * g0.y; a2 += w * g1.x;
    }
    __half2 o[4];
#pragma unroll
    for (int i = 0; i < 4; i++) {
        int c0 = h * 8 + 2 * i, c1 = c0 + 1;
        float t0 = sb[c0] + a0 * sW[c0] + a1 * sW[16 + c0] + a2 * sW[32 + c0];
        float t1 = sb[c1] + a0 * sW[c1] + a1 * sW[16 + c1] + a2 * sW[32 + c1];
        t0 = t0 > 0.f ? t0 : 0.01f * t0;
        t1 = t1 > 0.f ? t1 : 0.01f * t1;
        o[i] = __floats2half2_rn(t0, t1);
    }
    *(uint4*)(g_h1 + (size_t)v * 256 + t * 8) = *(uint4*)o;  // 512B coalesced per warp
}

// Accumulate one 32B row (uint4 of half2) into agg[8] with weight w.
__device__ __forceinline__ void acc_row(float* agg, uint4 raw, float w) {
    __half2* hp = (__half2*)&raw;
#pragma unroll
    for (int i = 0; i < 4; i++) {
        float2 f = __half22float2(hp[i]);
        agg[2 * i] += w * f.x;
        agg[2 * i + 1] += w * f.y;
    }
}

// Gather loop with chunk-4 MLP + scalar tail over [v][256] half array.
__device__ __forceinline__ void gather_agg(const __half* __restrict__ src,
                                           float* agg, int v, int t, float swt) {
    {
        uint4 raw = *(const uint4*)(src + (size_t)v * 256 + t * 8);
        __half2* hp = (__half2*)&raw;
#pragma unroll
        for (int i = 0; i < 4; i++) {
            float2 f = __half22float2(hp[i]);
            agg[2 * i] = swt * f.x;
            agg[2 * i + 1] = swt * f.y;
        }
    }
    int j = __ldg(&g_rowptr[v]);
    int r1 = __ldg(&g_rowptr[v + 1]);
    for (; j + 4 <= r1; j += 4) {
        int2 cw0 = __ldg(&g_cw[j]);
        int2 cw1 = __ldg(&g_cw[j + 1]);
        int2 cw2 = __ldg(&g_cw[j + 2]);
        int2 cw3 = __ldg(&g_cw[j + 3]);
        uint4 ra = *(const uint4*)(src + (size_t)cw0.x * 256 + t * 8);
        uint4 rb = *(const uint4*)(src + (size_t)cw1.x * 256 + t * 8);
        uint4 rc = *(const uint4*)(src + (size_t)cw2.x * 256 + t * 8);
        uint4 rd = *(const uint4*)(src + (size_t)cw3.x * 256 + t * 8);
        acc_row(agg, ra, __int_as_float(cw0.y));
        acc_row(agg, rb, __int_as_float(cw1.y));
        acc_row(agg, rc, __int_as_float(cw2.y));
        acc_row(agg, rd, __int_as_float(cw3.y));
    }
    for (; j < r1; j++) {
        int2 cw = __ldg(&g_cw[j]);
        uint4 raw = *(const uint4*)(src + (size_t)cw.x * 256 + t * 8);
        acc_row(agg, raw, __int_as_float(cw.y));
    }
}

// Layer 2: h1 -> h2.
__global__ void layer2_kernel(const float* __restrict__ W2,
                              const float* __restrict__ b2, int V) {
    __shared__ float sW[256], sb[16];
    sW[threadIdx.x] = W2[threadIdx.x];
    if (threadIdx.x < 16) sb[threadIdx.x] = b2[threadIdx.x];
    __syncthreads();
    int v = blockIdx.x * 8 + (threadIdx.x >> 5);
    if (v >= V) return;
    int t = threadIdx.x & 31;
    int h = t & 1;
    float di = __ldg(&g_dinv[v]);
    float agg[8];
    gather_agg(g_h1, agg, v, t, di * di);

    float po[16];
#pragma unroll
    for (int c = 0; c < 16; c++) {
        float acc = 0.f;
#pragma unroll
        for (int i = 0; i < 8; i++) acc += agg[i] * sW[(h * 8 + i) * 16 + c];
        po[c] = acc;
    }
    __half2 o[4];
#pragma unroll
    for (int i = 0; i < 4; i++) {
        int c0 = h * 8 + 2 * i, c1 = c0 + 1;
        int pc0 = (1 - h) * 8 + 2 * i, pc1 = pc0 + 1;
        float r0 = __shfl_xor_sync(0xFFFFFFFFu, po[pc0], 1);
        float r1v = __shfl_xor_sync(0xFFFFFFFFu, po[pc1], 1);
        float t0 = po[c0] + r0 + sb[c0];
        float t1 = po[c1] + r1v + sb[c1];
        t0 = t0 > 0.f ? t0 : 0.01f * t0;
        t1 = t1 > 0.f ? t1 : 0.01f * t1;
        o[i] = __floats2half2_rn(t0, t1);
    }
    *(uint4*)(g_h2 + (size_t)v * 256 + t * 8) = *(uint4*)o;
}

// Layer 3: h2 -> offs(3); v = x + offs; writes d_out and g_v4T[v][b] (coalesced).
__global__ void layer3_kernel(const float* __restrict__ x,
                              const float* __restrict__ W3,
                              const float* __restrict__ b3,
                              float* __restrict__ out, int V, int E) {
    __shared__ float sW[48], sb[3];
    if (threadIdx.x < 48) sW[threadIdx.x] = W3[threadIdx.x];
    if (threadIdx.x < 3) sb[threadIdx.x] = b3[threadIdx.x];
    __syncthreads();
    int v = blockIdx.x * 8 + (threadIdx.x >> 5);
    if (v >= V) return;
    int t = threadIdx.x & 31;
    int b = t >> 1, h = t & 1;
    float di = __ldg(&g_dinv[v]);
    float agg[8];
    gather_agg(g_h2, agg, v, t, di * di);

    float po[3];
#pragma unroll
    for (int p = 0; p < 3; p++) {
        float acc = 0.f;
#pragma unroll
        for (int i = 0; i < 8; i++) acc += agg[i] * sW[(h * 8 + i) * 3 + p];
        po[p] = acc;
    }
    float offs[3];
#pragma unroll
    for (int p = 0; p < 3; p++)
        offs[p] = po[p] + __shfl_xor_sync(0xFFFFFFFFu, po[p], 1) + sb[p];

    if (h == 0) {
        size_t n = (size_t)b * V + v;
        const float* xr = x + n * 3;  // fp32 original verts (output-critical)
        float vx = offs[0] + xr[0];
        float vy = offs[1] + xr[1];
        float vz = offs[2] + xr[2];
        size_t o = ((size_t)b * (V + E) + v) * 3;
        out[o + 0] = vx;
        out[o + 1] = vy;
        out[o + 2] = vz;
        // 16 h==0 lanes write consecutive b: one 256B contiguous run per warp
        g_v4T[(size_t)v * MAXB + b] = make_float4(vx, vy, vz, 0.f);
    }
}

// Midpoints: thread per edge x 4-batch slice. Per endpoint, the 4 batch reads
// are contiguous 64B runs in v4T (full sector use, high MLP).
__global__ void mid_kernel(const int* __restrict__ edges, float* __restrict__ out,
                           int V, int E) {
    int e = blockIdx.x * blockDim.x + threadIdx.x;
    if (e >= E) return;
    int b0 = blockIdx.y * 4;
    int2 sd = *(const int2*)(edges + 2 * e);
    const float4* ps = g_v4T + (size_t)sd.x * MAXB + b0;
    const float4* pd = g_v4T + (size_t)sd.y * MAXB + b0;
    float4 s0 = ps[0], s1 = ps[1], s2 = ps[2], s3 = ps[3];
    float4 d0 = pd[0], d1 = pd[1], d2 = pd[2], d3 = pd[3];
#pragma unroll
    for (int k = 0; k < 4; k++) {
        float4 vs = (k == 0) ? s0 : (k == 1) ? s1 : (k == 2) ? s2 : s3;
        float4 vd = (k == 0) ? d0 : (k == 1) ? d1 : (k == 2) ? d2 : d3;
        float* m = out + ((size_t)(b0 + k) * (V + E) + V + (size_t)e) * 3;
        m[0] = 0.5f * (vs.x + vd.x);
        m[1] = 0.5f * (vs.y + vd.y);
        m[2] = 0.5f * (vs.z + vd.z);
    }
}

// Broadcast faces across B (float4-vectorized; exact below 2^24).
__global__ void faces_kernel(const int* __restrict__ faces, float* __restrict__ out,
                             int perB, int B) {
    int i4 = blockIdx.x * blockDim.x + threadIdx.x;
    int n4 = perB >> 2;
    if (i4 < n4) {
        int4 f = ((const int4*)faces)[i4];
        float4 vf = make_float4((float)f.x, (float)f.y, (float)f.z, (float)f.w);
#pragma unroll
        for (int b = 0; b < MAXB; b++)
            if (b < B) ((float4*)(out + (size_t)b * perB))[i4] = vf;
    } else {
        int i = (n4 << 2) + (i4 - n4);  // scalar tail
        if (i < perB) {
            float vf = (float)faces[i];
            for (int b = 0; b < B; b++) out[(size_t)b * perB + i] = vf;
        }
    }
}

extern "C" void kernel_launch(void* const* d_in, const int* in_sizes, int n_in,
                              void* d_out, int out_size) {
    const float* verts = (const float*)d_in[0];
    const int*   edges = (const int*)d_in[1];
    const int*   faces = (const int*)d_in[2];
    const float* W1 = (const float*)d_in[3];
    const float* b1 = (const float*)d_in[4];
    const float* W2 = (const float*)d_in[5];
    const float* b2 = (const float*)d_in[6];
    const float* W3 = (const float*)d_in[7];
    const float* b3 = (const float*)d_in[8];
    float* out = (float*)d_out;

    const int B = 16;
    int E = in_sizes[1] / 2;
    int Fsub = in_sizes[2] / 3;
    int V = in_sizes[0] / (B * 3);
    int nScanBlocks = (V + 1023) / 1024;

    // Side stream + events (host-side objects only; created once).
    static cudaStream_t s2 = nullptr;
    static cudaEvent_t evFork = nullptr, evPad = nullptr, evJoin = nullptr;
    if (s2 == nullptr) {
        cudaStreamCreateWithFlags(&s2, cudaStreamNonBlocking);
        cudaEventCreateWithFlags(&evFork, cudaEventDisableTiming);
        cudaEventCreateWithFlags(&evPad, cudaEventDisableTiming);
        cudaEventCreateWithFlags(&evJoin, cudaEventDisableTiming);
    }

    long long vertsOut = (long long)B * (V + E) * 3;
    long long facesOut = (long long)B * Fsub * 3;
    bool doFaces = ((long long)out_size >= vertsOut + facesOut);

    // Fork: padT (needed before layer1) then faces broadcast on the side stream.
    cudaEventRecord(evFork, 0);
    cudaStreamWaitEvent(s2, evFork, 0);
    padT_kernel<<<(V + 15) / 16, 256, 0, s2>>>(verts, V);
    cudaEventRecord(evPad, s2);
    if (doFaces) {
        int perB = Fsub * 3;
        int n4 = perB / 4;
        int totalThreads = n4 + (perB - n4 * 4);
        faces_kernel<<<(totalThreads + 255) / 256, 256, 0, s2>>>(
            faces, out + vertsOut, perB, B);
    }
    cudaEventRecord(evJoin, s2);

    // CSR build on main stream (runs concurrently with padT/faces).
    zero_kernel<<<(V + 255) / 256, 256>>>(V);
    count_kernel<<<(E + 255) / 256, 256>>>(edges, E);
    scanA_kernel<<<nScanBlocks, 1024>>>(V);
    scanB_kernel<<<1, 128>>>(nScanBlocks, V);
    scanC_kernel<<<(V + 255) / 256, 256>>>(V);
    scatter_kernel<<<(E + 255) / 256, 256>>>(edges, E);

    // Join padT before the layers need g_xT.
    cudaStreamWaitEvent(0, evPad, 0);

    // GCN layers: warp per vertex, all batches at once
    int vblocks = (V + 7) / 8;
    layer1_kernel<<<vblocks, 256>>>(W1, b1, V);
    layer2_kernel<<<vblocks, 256>>>(W2, b2, V);
    layer3_kernel<<<vblocks, 256>>>(verts, W3, b3, out, V, E);

    // Midpoints (4-way batch split; contiguous v4T reads)
    dim3 midGrid((E + 255) / 256, 4);
    mid_kernel<<<midGrid, 256>>>(edges, out, V, E);

    // Join the faces branch back into the main stream.
    cudaStreamWaitEvent(0, evJoin, 0);
}